// round 12
// baseline (speedup 1.0000x reference)
#include <cuda_runtime.h>
#include <cuda_bf16.h>

#define JAX_PARTITIONABLE 1

// ---------------- scratch (__device__ globals; no allocation) ----------------
__device__ float g_T[8192 * 128];          // X_in @ theta
__device__ float g_U[8192 * 128];          // xi @ w_trans0
__device__ float g_U1[8192 * 128];         // xi @ w_trans1
__device__ float g_X[8192 * 128];          // X1 then X2
__device__ float g_msg[4096 * 128];        // edge messages (ew-scaled)
__device__ float g_msgP[8 * 4096 * 128];   // split-K partials for Hs GEMM
__device__ float g_ZP[4 * 8192 * 128];     // split-K partials for Ht^T GEMM
__device__ int   g_cnt[64];                // per-tile split counters (self-reset)

// ------------------------------- helpers ------------------------------------
__device__ __forceinline__ unsigned rotl32(unsigned v, int s) {
    return __funnelshift_l(v, v, s);
}

// bf16 2-way split of a k-pair (f0 = even k, f1 = odd k) -> packed hi, lo u32.
__device__ __forceinline__ void split_pair(float f0, float f1,
                                           unsigned& H, unsigned& L) {
    __nv_bfloat162 h = __floats2bfloat162_rn(f0, f1);
    float r0 = f0 - __bfloat162float(h.x);
    float r1 = f1 - __bfloat162float(h.y);
    __nv_bfloat162 l = __floats2bfloat162_rn(r0, r1);
    H = *reinterpret_cast<unsigned*>(&h);
    L = *reinterpret_cast<unsigned*>(&l);
}

// m16n8k16 bf16 mma, fp32 accumulate
__device__ __forceinline__ void mma16(float c[4], const unsigned a[4], const unsigned b[2]) {
    asm("mma.sync.aligned.m16n8k16.row.col.f32.bf16.bf16.f32 "
        "{%0,%1,%2,%3},{%4,%5,%6,%7},{%8,%9},{%0,%1,%2,%3};"
        : "+f"(c[0]), "+f"(c[1]), "+f"(c[2]), "+f"(c[3])
        : "r"(a[0]), "r"(a[1]), "r"(a[2]), "r"(a[3]), "r"(b[0]), "r"(b[1]));
}

// JAX threefry2x32, key = (0, 42). Random bits for flat element j of (8192,128).
__device__ __forceinline__ unsigned jax_dropout_bits(unsigned j) {
    const unsigned k0 = 0u, k1 = 42u;
    const unsigned ks2 = k0 ^ k1 ^ 0x1BD11BDAu;
    unsigned x0, x1;
#if JAX_PARTITIONABLE
    x0 = 0u + k0;
    x1 = j + k1;
#else
    const unsigned HALF = 524288u;
    unsigned i = (j < HALF) ? j : (j - HALF);
    x0 = i + k0;
    x1 = (i + HALF) + k1;
#endif
#define TFR(r) do { x0 += x1; x1 = rotl32(x1, (r)); x1 ^= x0; } while (0)
    TFR(13); TFR(15); TFR(26); TFR(6);   x0 += k1;  x1 += ks2 + 1u;
    TFR(17); TFR(29); TFR(16); TFR(24);  x0 += ks2; x1 += k0 + 2u;
    TFR(13); TFR(15); TFR(26); TFR(6);   x0 += k0;  x1 += k1 + 3u;
    TFR(17); TFR(29); TFR(16); TFR(24);  x0 += k1;  x1 += ks2 + 4u;
    TFR(13); TFR(15); TFR(26); TFR(6);   x0 += ks2; x1 += k0 + 5u;
#undef TFR
#if JAX_PARTITIONABLE
    return x0 ^ x1;
#else
    return (j < 524288u) ? x0 : x1;
#endif
}

// ============= 3-term bf16-split GEMM, 8-warp CTA, fused epilogue ============
// C[M,128] = op(A) @ B;  B is [K,128] row-major fp32.
// 256 threads = 8 warps (4M x 2N), warp tile 32x64, k32 per iteration,
// double-buffered smem, register prefetch, 2 CTAs/SM.
// SMEM per buffer (u32):
//   AsH[128 rows][20] (16 k-pairs + 4 pad) 2560 ; AsL same
//   BsH[16 k-pairs][136]                   2176 ; BsL same
static const int ASZ = 2560, BSZ = 2176;
static const int BUF_STRIDE = 2 * ASZ + 2 * BSZ;   // 9472 u32
static const int SM_BYTES = BUF_STRIDE * 2 * 4;    // 75776 B

// epilogue modes
#define EPI_NONE 0
#define EPI_MSG  1
#define EPI_X1   2
#define EPI_X2   3

template <bool TRANS_A>
__device__ __forceinline__ float4 loadA(const float* __restrict__ A, int lda,
                                        int m0, int kc, int row, int kq) {
    if (TRANS_A) {
        const float* p = A + (size_t)(kc + kq * 4) * lda + m0 + row;
        float4 v;
        v.x = p[0];
        v.y = p[(size_t)lda];
        v.z = p[2 * (size_t)lda];
        v.w = p[3 * (size_t)lda];
        return v;
    } else {
        return *(const float4*)(A + (size_t)(m0 + row) * lda + kc + kq * 4);
    }
}

__device__ __forceinline__ void stA(unsigned* __restrict__ AsH,
                                    unsigned* __restrict__ AsL,
                                    int row, int kq, float4 v) {
    unsigned h0, l0, h1, l1;
    split_pair(v.x, v.y, h0, l0);
    split_pair(v.z, v.w, h1, l1);
    *(uint2*)&AsH[row * 20 + 2 * kq] = make_uint2(h0, h1);
    *(uint2*)&AsL[row * 20 + 2 * kq] = make_uint2(l0, l1);
}

__device__ __forceinline__ void stB(unsigned* __restrict__ BsH,
                                    unsigned* __restrict__ BsL,
                                    int p, int n, float4 r0, float4 r1) {
    unsigned h[4], l[4];
    split_pair(r0.x, r1.x, h[0], l[0]);
    split_pair(r0.y, r1.y, h[1], l[1]);
    split_pair(r0.z, r1.z, h[2], l[2]);
    split_pair(r0.w, r1.w, h[3], l[3]);
    *(uint4*)&BsH[p * 136 + n] = make_uint4(h[0], h[1], h[2], h[3]);
    *(uint4*)&BsL[p * 136 + n] = make_uint4(l[0], l[1], l[2], l[3]);
}

template <bool TRANS_A, int EPI>
__global__ __launch_bounds__(256, 2)
void gemm_fused(const float* __restrict__ A, const float* __restrict__ B,
                float* __restrict__ Cp, int lda, int k_iters,
                const float* __restrict__ aux,   // ew (MSG) or U (X1/X2)
                const float* __restrict__ bias,  // b (X1/X2)
                float* __restrict__ outF)        // final output array
{
    extern __shared__ unsigned sm[];
    const int tid = threadIdx.x;
    const int lane = tid & 31;
    const int wid = tid >> 5;              // 0..7
    const int wm = (wid & 3) * 32;
    const int wn = (wid >> 2) * 64;
    const int g = lane >> 2;               // 0..7
    const int t = lane & 3;                // 0..3
    const int mblk = blockIdx.x;
    const int split = blockIdx.y;
    const int gx = gridDim.x;
    const int m0 = mblk * 128;
    const int k00 = split * k_iters * 32;

    // staging geometry: A -> 4 float4 tasks; B -> 2 (pair of float4) tasks
    int ar_row[4], ar_kq[4];
#pragma unroll
    for (int r = 0; r < 4; ++r) {
        int task = tid + r * 256;
        if (TRANS_A) { ar_row[r] = task & 127; ar_kq[r] = task >> 7; }   // 0..7
        else         { ar_row[r] = task >> 3;  ar_kq[r] = task & 7;  }
    }
    int b_p[2], b_n[2];
#pragma unroll
    for (int r = 0; r < 2; ++r) {
        int task = tid + r * 256;
        b_p[r] = task >> 5;                // 0..15 (k-pair)
        b_n[r] = (task & 31) * 4;          // n quad
    }

    float acc[2][8][4];
#pragma unroll
    for (int mt = 0; mt < 2; ++mt)
#pragma unroll
        for (int nt = 0; nt < 8; ++nt)
#pragma unroll
            for (int i = 0; i < 4; ++i) acc[mt][nt][i] = 0.f;

    float4 av[4], bv0[2], bv1[2];

    // prologue: load + stage tile 0 into buffer 0
    int kc = k00;
#pragma unroll
    for (int r = 0; r < 4; ++r)
        av[r] = loadA<TRANS_A>(A, lda, m0, kc, ar_row[r], ar_kq[r]);
#pragma unroll
    for (int r = 0; r < 2; ++r) {
        bv0[r] = *(const float4*)(B + (size_t)(kc + 2 * b_p[r]) * 128 + b_n[r]);
        bv1[r] = *(const float4*)(B + (size_t)(kc + 2 * b_p[r] + 1) * 128 + b_n[r]);
    }
#pragma unroll
    for (int r = 0; r < 4; ++r) stA(sm, sm + ASZ, ar_row[r], ar_kq[r], av[r]);
#pragma unroll
    for (int r = 0; r < 2; ++r)
        stB(sm + 2 * ASZ, sm + 2 * ASZ + BSZ, b_p[r], b_n[r], bv0[r], bv1[r]);
    __syncthreads();

    for (int it = 0; it < k_iters; ++it) {
        const unsigned* cur = sm + (it & 1) * BUF_STRIDE;
        const unsigned* cAH = cur;
        const unsigned* cAL = cur + ASZ;
        const unsigned* cBH = cur + 2 * ASZ;
        const unsigned* cBL = cur + 2 * ASZ + BSZ;
        const bool hn = (it + 1 < k_iters);

        if (hn) {  // next-tile global loads, hidden under mmas
            kc = k00 + (it + 1) * 32;
#pragma unroll
            for (int r = 0; r < 4; ++r)
                av[r] = loadA<TRANS_A>(A, lda, m0, kc, ar_row[r], ar_kq[r]);
#pragma unroll
            for (int r = 0; r < 2; ++r) {
                bv0[r] = *(const float4*)(B + (size_t)(kc + 2 * b_p[r]) * 128 + b_n[r]);
                bv1[r] = *(const float4*)(B + (size_t)(kc + 2 * b_p[r] + 1) * 128 + b_n[r]);
            }
        }

#pragma unroll
        for (int ks = 0; ks < 2; ++ks) {          // two k16 sub-steps
            const int pb = ks * 8;
            unsigned aH[2][4], aL[2][4];
#pragma unroll
            for (int mt = 0; mt < 2; ++mt) {
                const int r0 = (wm + mt * 16 + g) * 20;
                const int r1 = r0 + 8 * 20;
                aH[mt][0] = cAH[r0 + pb + t];
                aH[mt][1] = cAH[r1 + pb + t];
                aH[mt][2] = cAH[r0 + pb + t + 4];
                aH[mt][3] = cAH[r1 + pb + t + 4];
                aL[mt][0] = cAL[r0 + pb + t];
                aL[mt][1] = cAL[r1 + pb + t];
                aL[mt][2] = cAL[r0 + pb + t + 4];
                aL[mt][3] = cAL[r1 + pb + t + 4];
            }
#pragma unroll
            for (int nt = 0; nt < 8; ++nt) {
                const int nb = wn + nt * 8 + g;
                const int j0 = (pb + t) * 136 + nb;
                const int j1 = (pb + t + 4) * 136 + nb;
                unsigned bH[2] = { cBH[j0], cBH[j1] };
                unsigned bL[2] = { cBL[j0], cBL[j1] };
#pragma unroll
                for (int mt = 0; mt < 2; ++mt) {
                    mma16(acc[mt][nt], aH[mt], bH);   // hi*hi
                    mma16(acc[mt][nt], aL[mt], bH);   // lo*hi
                    mma16(acc[mt][nt], aH[mt], bL);   // hi*lo
                }
            }
        }

        if (hn) {
            unsigned* nb2 = sm + ((it + 1) & 1) * BUF_STRIDE;
#pragma unroll
            for (int r = 0; r < 4; ++r)
                stA(nb2, nb2 + ASZ, ar_row[r], ar_kq[r], av[r]);
#pragma unroll
            for (int r = 0; r < 2; ++r)
                stB(nb2 + 2 * ASZ, nb2 + 2 * ASZ + BSZ, b_p[r], b_n[r], bv0[r], bv1[r]);
        }
        __syncthreads();
    }

    // write (partial) tile
    float* Cb = Cp + (size_t)split * gx * (128 * 128) + (size_t)m0 * 128;
#pragma unroll
    for (int mt = 0; mt < 2; ++mt)
#pragma unroll
        for (int nt = 0; nt < 8; ++nt) {
            const int r = wm + mt * 16 + g;
            const int c = wn + nt * 8 + t * 2;
            *(float2*)&Cb[(size_t)r * 128 + c] =
                make_float2(acc[mt][nt][0], acc[mt][nt][1]);
            *(float2*)&Cb[(size_t)(r + 8) * 128 + c] =
                make_float2(acc[mt][nt][2], acc[mt][nt][3]);
        }

    if (EPI == EPI_NONE) return;

    // ---- fused split-K reduction + epilogue (last CTA per tile) ----
    __syncthreads();
    __shared__ int s_fin;
    if (tid == 0) {
        __threadfence();
        int old = atomicAdd(&g_cnt[mblk], 1);
        int fin = (old == (int)gridDim.y - 1);
        s_fin = fin;
        if (fin) g_cnt[mblk] = 0;   // self-reset for next launch
    }
    __syncthreads();
    if (!s_fin) return;
    __threadfence();

    const int S = gridDim.y;
    const float* Pt = Cp + (size_t)m0 * 128;
    for (int v = tid; v < 4096; v += 256) {        // float4 over 128x128 tile
        float4 s = make_float4(0.f, 0.f, 0.f, 0.f);
        for (int j = 0; j < S; ++j) {              // fixed order: deterministic
            float4 p = *(const float4*)&Pt[(size_t)j * gx * (128 * 128) + v * 4];
            s.x += p.x; s.y += p.y; s.z += p.z; s.w += p.w;
        }
        const int row = v >> 5;
        const int col = (v & 31) * 4;
        float* o = outF + (size_t)(m0 + row) * 128 + col;
        if (EPI == EPI_MSG) {
            const float w = aux[m0 + row];
            o[0] = s.x * w; o[1] = s.y * w; o[2] = s.z * w; o[3] = s.w * w;
        } else {
            const float* u = aux + (size_t)(m0 + row) * 128 + col;
            float e[4] = { s.x + u[0] + bias[col],
                           s.y + u[1] + bias[col + 1],
                           s.z + u[2] + bias[col + 2],
                           s.w + u[3] + bias[col + 3] };
#pragma unroll
            for (int q = 0; q < 4; ++q) {
                float z = e[q];
                z = (z >= 0.f) ? z : 0.01f * z;                  // lrelu
                if (EPI == EPI_X1) {
                    unsigned jj = (unsigned)((m0 + row) * 128 + col + q);
                    z = (jax_dropout_bits(jj) & 0x80000000u) ? 0.f : (z + z);
                } else {
                    z = (z >= 0.f) ? z : 0.01f * z;              // second lrelu
                }
                e[q] = z;
            }
            o[0] = e[0]; o[1] = e[1]; o[2] = e[2]; o[3] = e[3];
        }
    }
}

struct GemmJob { const float* A; const float* B; float* C; };

__global__ __launch_bounds__(256, 2)
void gemm_small3(GemmJob j0, GemmJob j1, GemmJob j2);   // fwd decl style kept simple

// small GEMMs reuse the fused kernel body with EPI_NONE via a thin wrapper:
__global__ __launch_bounds__(256, 2)
void gemm_small3_impl(GemmJob j0, GemmJob j1, GemmJob j2)
{
    // dispatch by z; replicate gemm_fused<false,EPI_NONE> semantics by calling
    // the same code path through a device function is heavy; instead just
    // inline-launch: A [M,128] @ B [128,128], k_iters=4, split=0.
    GemmJob j = (blockIdx.z == 0) ? j0 : ((blockIdx.z == 1) ? j1 : j2);
    // --- duplicated minimal body (EPI_NONE, TRANS_A=false) ---
    extern __shared__ unsigned sm[];
    const int tid = threadIdx.x;
    const int lane = tid & 31;
    const int wid = tid >> 5;
    const int wm = (wid & 3) * 32;
    const int wn = (wid >> 2) * 64;
    const int g = lane >> 2;
    const int t = lane & 3;
    const int m0 = blockIdx.x * 128;
    const int k_iters = 4;

    int ar_row[4], ar_kq[4];
#pragma unroll
    for (int r = 0; r < 4; ++r) {
        int task = tid + r * 256;
        ar_row[r] = task >> 3; ar_kq[r] = task & 7;
    }
    int b_p[2], b_n[2];
#pragma unroll
    for (int r = 0; r < 2; ++r) {
        int task = tid + r * 256;
        b_p[r] = task >> 5; b_n[r] = (task & 31) * 4;
    }

    float acc[2][8][4];
#pragma unroll
    for (int mt = 0; mt < 2; ++mt)
#pragma unroll
        for (int nt = 0; nt < 8; ++nt)
#pragma unroll
            for (int i = 0; i < 4; ++i) acc[mt][nt][i] = 0.f;

    float4 av[4], bv0[2], bv1[2];
    int kc = 0;
#pragma unroll
    for (int r = 0; r < 4; ++r)
        av[r] = *(const float4*)(j.A + (size_t)(m0 + ar_row[r]) * 128 + ar_kq[r] * 4);
#pragma unroll
    for (int r = 0; r < 2; ++r) {
        bv0[r] = *(const float4*)(j.B + (size_t)(2 * b_p[r]) * 128 + b_n[r]);
        bv1[r] = *(const float4*)(j.B + (size_t)(2 * b_p[r] + 1) * 128 + b_n[r]);
    }
#pragma unroll
    for (int r = 0; r < 4; ++r) stA(sm, sm + ASZ, ar_row[r], ar_kq[r], av[r]);
#pragma unroll
    for (int r = 0; r < 2; ++r)
        stB(sm + 2 * ASZ, sm + 2 * ASZ + BSZ, b_p[r], b_n[r], bv0[r], bv1[r]);
    __syncthreads();

    for (int it = 0; it < k_iters; ++it) {
        const unsigned* cur = sm + (it & 1) * BUF_STRIDE;
        const unsigned* cAH = cur;
        const unsigned* cAL = cur + ASZ;
        const unsigned* cBH = cur + 2 * ASZ;
        const unsigned* cBL = cur + 2 * ASZ + BSZ;
        const bool hn = (it + 1 < k_iters);
        if (hn) {
            kc = (it + 1) * 32;
#pragma unroll
            for (int r = 0; r < 4; ++r)
                av[r] = *(const float4*)(j.A + (size_t)(m0 + ar_row[r]) * 128 + kc + ar_kq[r] * 4);
#pragma unroll
            for (int r = 0; r < 2; ++r) {
                bv0[r] = *(const float4*)(j.B + (size_t)(kc + 2 * b_p[r]) * 128 + b_n[r]);
                bv1[r] = *(const float4*)(j.B + (size_t)(kc + 2 * b_p[r] + 1) * 128 + b_n[r]);
            }
        }
#pragma unroll
        for (int ks = 0; ks < 2; ++ks) {
            const int pb = ks * 8;
            unsigned aH[2][4], aL[2][4];
#pragma unroll
            for (int mt = 0; mt < 2; ++mt) {
                const int r0 = (wm + mt * 16 + g) * 20;
                const int r1 = r0 + 8 * 20;
                aH[mt][0] = cAH[r0 + pb + t];
                aH[mt][1] = cAH[r1 + pb + t];
                aH[mt][2] = cAH[r0 + pb + t + 4];
                aH[mt][3] = cAH[r1 + pb + t + 4];
                aL[mt][0] = cAL[r0 + pb + t];
                aL[mt][1] = cAL[r1 + pb + t];
                aL[mt][2] = cAL[r0 + pb + t + 4];
                aL[mt][3] = cAL[r1 + pb + t + 4];
            }
#pragma unroll
            for (int nt = 0; nt < 8; ++nt) {
                const int nb = wn + nt * 8 + g;
                const int j0i = (pb + t) * 136 + nb;
                const int j1i = (pb + t + 4) * 136 + nb;
                unsigned bH[2] = { cBH[j0i], cBH[j1i] };
                unsigned bL[2] = { cBL[j0i], cBL[j1i] };
#pragma unroll
                for (int mt = 0; mt < 2; ++mt) {
                    mma16(acc[mt][nt], aH[mt], bH);
                    mma16(acc[mt][nt], aL[mt], bH);
                    mma16(acc[mt][nt], aH[mt], bL);
                }
            }
        }
        if (hn) {
            unsigned* nb2 = sm + ((it + 1) & 1) * BUF_STRIDE;
#pragma unroll
            for (int r = 0; r < 4; ++r) stA(nb2, nb2 + ASZ, ar_row[r], ar_kq[r], av[r]);
#pragma unroll
            for (int r = 0; r < 2; ++r)
                stB(nb2 + 2 * ASZ, nb2 + 2 * ASZ + BSZ, b_p[r], b_n[r], bv0[r], bv1[r]);
        }
        __syncthreads();
    }

    float* Cb = j.C + (size_t)m0 * 128;
#pragma unroll
    for (int mt = 0; mt < 2; ++mt)
#pragma unroll
        for (int nt = 0; nt < 8; ++nt) {
            const int r = wm + mt * 16 + g;
            const int c = wn + nt * 8 + t * 2;
            *(float2*)&Cb[(size_t)r * 128 + c] =
                make_float2(acc[mt][nt][0], acc[mt][nt][1]);
            *(float2*)&Cb[(size_t)(r + 8) * 128 + c] =
                make_float2(acc[mt][nt][2], acc[mt][nt][3]);
        }
}

__global__ void fc_k(const float* __restrict__ X, const float* __restrict__ state,
                     const float* __restrict__ fcw, const float* __restrict__ fcb,
                     float* __restrict__ out)
{
    const int n = blockIdx.x * 256 + threadIdx.x;
    const float4* xr = (const float4*)(X + (size_t)n * 128);
    const float4* w4 = (const float4*)fcw;
    float s = 0.f;
#pragma unroll
    for (int i = 0; i < 32; ++i) {
        float4 a = xr[i], b = w4[i];
        s += a.x * b.x + a.y * b.y + a.z * b.z + a.w * b.w;
    }
    out[n] = s + state[n] * fcw[128] + fcb[0];
}

// --------------------------------- launch ------------------------------------
extern "C" void kernel_launch(void* const* d_in, const int* in_sizes, int n_in,
                              void* d_out, int out_size)
{
    const float* xi   = (const float*)d_in[0];
    const float* x    = (const float*)d_in[1];
    const float* Ht   = (const float*)d_in[2];
    const float* Hs   = (const float*)d_in[3];
    const float* st   = (const float*)d_in[4];
    const float* w0   = (const float*)d_in[5];
    const float* th0  = (const float*)d_in[6];
    const float* ew0  = (const float*)d_in[7];
    const float* b0   = (const float*)d_in[8];
    const float* w1   = (const float*)d_in[9];
    const float* th1  = (const float*)d_in[10];
    const float* ew1  = (const float*)d_in[11];
    const float* b1   = (const float*)d_in[12];
    const float* fcw  = (const float*)d_in[13];
    const float* fcb  = (const float*)d_in[14];
    float* out = (float*)d_out;

    float *T, *U, *U1, *X, *M, *MP, *ZP;
    cudaGetSymbolAddress((void**)&T,  g_T);
    cudaGetSymbolAddress((void**)&U,  g_U);
    cudaGetSymbolAddress((void**)&U1, g_U1);
    cudaGetSymbolAddress((void**)&X,  g_X);
    cudaGetSymbolAddress((void**)&M,  g_msg);
    cudaGetSymbolAddress((void**)&MP, g_msgP);
    cudaGetSymbolAddress((void**)&ZP, g_ZP);

    cudaFuncSetAttribute(gemm_fused<false, EPI_MSG>, cudaFuncAttributeMaxDynamicSharedMemorySize, SM_BYTES);
    cudaFuncSetAttribute(gemm_fused<true,  EPI_X1>,  cudaFuncAttributeMaxDynamicSharedMemorySize, SM_BYTES);
    cudaFuncSetAttribute(gemm_fused<true,  EPI_X2>,  cudaFuncAttributeMaxDynamicSharedMemorySize, SM_BYTES);
    cudaFuncSetAttribute(gemm_fused<false, EPI_NONE>,cudaFuncAttributeMaxDynamicSharedMemorySize, SM_BYTES);
    cudaFuncSetAttribute(gemm_small3_impl,           cudaFuncAttributeMaxDynamicSharedMemorySize, SM_BYTES);

    // independent small GEMMs: T = x@th0, U = xi@w0, U1 = xi@w1
    GemmJob j0 = { x,  th0, T  };
    GemmJob j1 = { xi, w0,  U  };
    GemmJob j2 = { xi, w1,  U1 };
    gemm_small3_impl<<<dim3(64, 1, 3), 256, SM_BYTES>>>(j0, j1, j2);

    // ---- layer 0 ----
    gemm_fused<false, EPI_MSG><<<dim3(32, 8), 256, SM_BYTES>>>(Hs, T, MP, 8192, 32, ew0, nullptr, M);
    gemm_fused<true,  EPI_X1 ><<<dim3(64, 4), 256, SM_BYTES>>>(Ht, M, ZP, 8192, 32, U,  b0, X);

    // ---- layer 1 ----
    GemmJob s1 = { X, th1, T };
    gemm_small3_impl<<<dim3(64, 1, 1), 256, SM_BYTES>>>(s1, s1, s1);
    gemm_fused<false, EPI_MSG><<<dim3(32, 8), 256, SM_BYTES>>>(Hs, T, MP, 8192, 32, ew1, nullptr, M);
    gemm_fused<true,  EPI_X2 ><<<dim3(64, 4), 256, SM_BYTES>>>(Ht, M, ZP, 8192, 32, U1, b1, X);

    // ---- head ----
    fc_k<<<32, 256>>>(X, st, fcw, fcb, out);
}

// round 13
// speedup vs baseline: 1.0641x; 1.0641x over previous
#include <cuda_runtime.h>
#include <cuda_bf16.h>

#define JAX_PARTITIONABLE 1

// ---------------- scratch (__device__ globals; no allocation) ----------------
__device__ float g_T[8192 * 128];          // X_in @ theta
__device__ float g_U[8192 * 128];          // xi @ w_trans0
__device__ float g_U1[8192 * 128];         // xi @ w_trans1
__device__ float g_X[8192 * 128];          // X1 then X2
__device__ float g_msg[4096 * 128];        // edge messages (ew-scaled)
__device__ float g_msgP[8 * 4096 * 128];   // split-K partials for Hs GEMM
__device__ float g_ZP[4 * 8192 * 128];     // split-K partials for Ht^T GEMM

// ------------------------------- helpers ------------------------------------
__device__ __forceinline__ unsigned rotl32(unsigned v, int s) {
    return __funnelshift_l(v, v, s);
}

// bf16 2-way split of a k-pair (f0 = even k, f1 = odd k) -> packed hi, lo u32.
__device__ __forceinline__ void split_pair(float f0, float f1,
                                           unsigned& H, unsigned& L) {
    __nv_bfloat162 h = __floats2bfloat162_rn(f0, f1);
    float r0 = f0 - __bfloat162float(h.x);
    float r1 = f1 - __bfloat162float(h.y);
    __nv_bfloat162 l = __floats2bfloat162_rn(r0, r1);
    H = *reinterpret_cast<unsigned*>(&h);
    L = *reinterpret_cast<unsigned*>(&l);
}

// m16n8k16 bf16 mma, fp32 accumulate
__device__ __forceinline__ void mma16(float c[4], const unsigned a[4], const unsigned b[2]) {
    asm("mma.sync.aligned.m16n8k16.row.col.f32.bf16.bf16.f32 "
        "{%0,%1,%2,%3},{%4,%5,%6,%7},{%8,%9},{%0,%1,%2,%3};"
        : "+f"(c[0]), "+f"(c[1]), "+f"(c[2]), "+f"(c[3])
        : "r"(a[0]), "r"(a[1]), "r"(a[2]), "r"(a[3]), "r"(b[0]), "r"(b[1]));
}

// JAX threefry2x32, key = (0, 42). Random bits for flat element j of (8192,128).
__device__ __forceinline__ unsigned jax_dropout_bits(unsigned j) {
    const unsigned k0 = 0u, k1 = 42u;
    const unsigned ks2 = k0 ^ k1 ^ 0x1BD11BDAu;
    unsigned x0, x1;
#if JAX_PARTITIONABLE
    x0 = 0u + k0;
    x1 = j + k1;
#else
    const unsigned HALF = 524288u;
    unsigned i = (j < HALF) ? j : (j - HALF);
    x0 = i + k0;
    x1 = (i + HALF) + k1;
#endif
#define TFR(r) do { x0 += x1; x1 = rotl32(x1, (r)); x1 ^= x0; } while (0)
    TFR(13); TFR(15); TFR(26); TFR(6);   x0 += k1;  x1 += ks2 + 1u;
    TFR(17); TFR(29); TFR(16); TFR(24);  x0 += ks2; x1 += k0 + 2u;
    TFR(13); TFR(15); TFR(26); TFR(6);   x0 += k0;  x1 += k1 + 3u;
    TFR(17); TFR(29); TFR(16); TFR(24);  x0 += k1;  x1 += ks2 + 4u;
    TFR(13); TFR(15); TFR(26); TFR(6);   x0 += ks2; x1 += k0 + 5u;
#undef TFR
#if JAX_PARTITIONABLE
    return x0 ^ x1;
#else
    return (j < 524288u) ? x0 : x1;
#endif
}

// ============== 3-term bf16-split GEMM, 8-warp CTA, 2 CTAs/SM ================
// C[M,128] = op(A) @ B;  B is [K,128] row-major fp32.
//   TRANS_A=false: A [M,K] row-major (row stride lda)
//   TRANS_A=true : A [K,M] row-major (row stride lda), used as A^T
// 256 threads = 8 warps (4M x 2N), warp tile 32x64, k32 per iteration,
// double-buffered smem, register prefetch, 1 sync/iter, 2 CTAs/SM.
// SMEM per buffer (u32):
//   AsH[128 rows][20] (16 k-pairs + 4 pad) 2560 ; AsL same
//   BsH[16 k-pairs][136] (128 n + 8 pad)   2176 ; BsL same
static const int ASZ = 2560, BSZ = 2176;
static const int BUF_STRIDE = 2 * ASZ + 2 * BSZ;   // 9472 u32
static const int SM_BYTES = BUF_STRIDE * 2 * 4;    // 75776 B

template <bool TRANS_A>
__device__ __forceinline__ float4 loadA(const float* __restrict__ A, int lda,
                                        int m0, int kc, int row, int kq) {
    if (TRANS_A) {
        const float* p = A + (size_t)(kc + kq * 4) * lda + m0 + row;
        float4 v;
        v.x = p[0];
        v.y = p[(size_t)lda];
        v.z = p[2 * (size_t)lda];
        v.w = p[3 * (size_t)lda];
        return v;
    } else {
        return *(const float4*)(A + (size_t)(m0 + row) * lda + kc + kq * 4);
    }
}

__device__ __forceinline__ void stA(unsigned* __restrict__ AsH,
                                    unsigned* __restrict__ AsL,
                                    int row, int kq, float4 v) {
    unsigned h0, l0, h1, l1;
    split_pair(v.x, v.y, h0, l0);
    split_pair(v.z, v.w, h1, l1);
    *(uint2*)&AsH[row * 20 + 2 * kq] = make_uint2(h0, h1);
    *(uint2*)&AsL[row * 20 + 2 * kq] = make_uint2(l0, l1);
}

__device__ __forceinline__ void stB(unsigned* __restrict__ BsH,
                                    unsigned* __restrict__ BsL,
                                    int p, int n, float4 r0, float4 r1) {
    unsigned h[4], l[4];
    split_pair(r0.x, r1.x, h[0], l[0]);
    split_pair(r0.y, r1.y, h[1], l[1]);
    split_pair(r0.z, r1.z, h[2], l[2]);
    split_pair(r0.w, r1.w, h[3], l[3]);
    *(uint4*)&BsH[p * 136 + n] = make_uint4(h[0], h[1], h[2], h[3]);
    *(uint4*)&BsL[p * 136 + n] = make_uint4(l[0], l[1], l[2], l[3]);
}

template <bool TRANS_A>
__device__ __forceinline__ void gemm8_body(
    const float* __restrict__ A, const float* __restrict__ B,
    float* __restrict__ Cp, int lda, int k_iters, int mblk, int split, int gx)
{
    extern __shared__ unsigned sm[];
    const int tid = threadIdx.x;
    const int lane = tid & 31;
    const int wid = tid >> 5;              // 0..7
    const int wm = (wid & 3) * 32;
    const int wn = (wid >> 2) * 64;
    const int g = lane >> 2;               // 0..7
    const int t = lane & 3;                // 0..3
    const int m0 = mblk * 128;
    const int k00 = split * k_iters * 32;

    // staging geometry: A -> 4 float4 tasks; B -> 2 (pair of float4) tasks
    int ar_row[4], ar_kq[4];
#pragma unroll
    for (int r = 0; r < 4; ++r) {
        int task = tid + r * 256;
        if (TRANS_A) { ar_row[r] = task & 127; ar_kq[r] = task >> 7; }   // 0..7
        else         { ar_row[r] = task >> 3;  ar_kq[r] = task & 7;  }
    }
    int b_p[2], b_n[2];
#pragma unroll
    for (int r = 0; r < 2; ++r) {
        int task = tid + r * 256;
        b_p[r] = task >> 5;                // 0..15 (k-pair)
        b_n[r] = (task & 31) * 4;          // n quad
    }

    float acc[2][8][4];
#pragma unroll
    for (int mt = 0; mt < 2; ++mt)
#pragma unroll
        for (int nt = 0; nt < 8; ++nt)
#pragma unroll
            for (int i = 0; i < 4; ++i) acc[mt][nt][i] = 0.f;

    float4 av[4], bv0[2], bv1[2];

    // prologue: load + stage tile 0 into buffer 0
    int kc = k00;
#pragma unroll
    for (int r = 0; r < 4; ++r)
        av[r] = loadA<TRANS_A>(A, lda, m0, kc, ar_row[r], ar_kq[r]);
#pragma unroll
    for (int r = 0; r < 2; ++r) {
        bv0[r] = *(const float4*)(B + (size_t)(kc + 2 * b_p[r]) * 128 + b_n[r]);
        bv1[r] = *(const float4*)(B + (size_t)(kc + 2 * b_p[r] + 1) * 128 + b_n[r]);
    }
#pragma unroll
    for (int r = 0; r < 4; ++r) stA(sm, sm + ASZ, ar_row[r], ar_kq[r], av[r]);
#pragma unroll
    for (int r = 0; r < 2; ++r)
        stB(sm + 2 * ASZ, sm + 2 * ASZ + BSZ, b_p[r], b_n[r], bv0[r], bv1[r]);
    __syncthreads();

    for (int it = 0; it < k_iters; ++it) {
        const unsigned* cur = sm + (it & 1) * BUF_STRIDE;
        const unsigned* cAH = cur;
        const unsigned* cAL = cur + ASZ;
        const unsigned* cBH = cur + 2 * ASZ;
        const unsigned* cBL = cur + 2 * ASZ + BSZ;
        const bool hn = (it + 1 < k_iters);

        if (hn) {  // next-tile global loads, hidden under mmas
            kc = k00 + (it + 1) * 32;
#pragma unroll
            for (int r = 0; r < 4; ++r)
                av[r] = loadA<TRANS_A>(A, lda, m0, kc, ar_row[r], ar_kq[r]);
#pragma unroll
            for (int r = 0; r < 2; ++r) {
                bv0[r] = *(const float4*)(B + (size_t)(kc + 2 * b_p[r]) * 128 + b_n[r]);
                bv1[r] = *(const float4*)(B + (size_t)(kc + 2 * b_p[r] + 1) * 128 + b_n[r]);
            }
        }

#pragma unroll
        for (int ks = 0; ks < 2; ++ks) {          // two k16 sub-steps
            const int pb = ks * 8;
            unsigned aH[2][4], aL[2][4];
#pragma unroll
            for (int mt = 0; mt < 2; ++mt) {
                const int r0 = (wm + mt * 16 + g) * 20;
                const int r1 = r0 + 8 * 20;
                aH[mt][0] = cAH[r0 + pb + t];
                aH[mt][1] = cAH[r1 + pb + t];
                aH[mt][2] = cAH[r0 + pb + t + 4];
                aH[mt][3] = cAH[r1 + pb + t + 4];
                aL[mt][0] = cAL[r0 + pb + t];
                aL[mt][1] = cAL[r1 + pb + t];
                aL[mt][2] = cAL[r0 + pb + t + 4];
                aL[mt][3] = cAL[r1 + pb + t + 4];
            }
#pragma unroll
            for (int nt = 0; nt < 8; ++nt) {
                const int nb = wn + nt * 8 + g;
                const int j0 = (pb + t) * 136 + nb;
                const int j1 = (pb + t + 4) * 136 + nb;
                unsigned bH[2] = { cBH[j0], cBH[j1] };
                unsigned bL[2] = { cBL[j0], cBL[j1] };
#pragma unroll
                for (int mt = 0; mt < 2; ++mt) {
                    mma16(acc[mt][nt], aH[mt], bH);   // hi*hi
                    mma16(acc[mt][nt], aL[mt], bH);   // lo*hi
                    mma16(acc[mt][nt], aH[mt], bL);   // hi*lo
                }
            }
        }

        if (hn) {
            unsigned* nb2 = sm + ((it + 1) & 1) * BUF_STRIDE;
#pragma unroll
            for (int r = 0; r < 4; ++r)
                stA(nb2, nb2 + ASZ, ar_row[r], ar_kq[r], av[r]);
#pragma unroll
            for (int r = 0; r < 2; ++r)
                stB(nb2 + 2 * ASZ, nb2 + 2 * ASZ + BSZ, b_p[r], b_n[r], bv0[r], bv1[r]);
        }
        __syncthreads();
    }

    float* Cb = Cp + (size_t)split * gx * (128 * 128) + (size_t)m0 * 128;
#pragma unroll
    for (int mt = 0; mt < 2; ++mt)
#pragma unroll
        for (int nt = 0; nt < 8; ++nt) {
            const int r = wm + mt * 16 + g;
            const int c = wn + nt * 8 + t * 2;
            *(float2*)&Cb[(size_t)r * 128 + c] =
                make_float2(acc[mt][nt][0], acc[mt][nt][1]);
            *(float2*)&Cb[(size_t)(r + 8) * 128 + c] =
                make_float2(acc[mt][nt][2], acc[mt][nt][3]);
        }
}

// ------------------------------ GEMM kernels ---------------------------------
template <bool TRANS_A>
__global__ __launch_bounds__(256, 2)
void gemm_big(const float* __restrict__ A, const float* __restrict__ B,
              float* __restrict__ Cp, int lda, int k_iters)
{
    gemm8_body<TRANS_A>(A, B, Cp, lda, k_iters, blockIdx.x, blockIdx.y, gridDim.x);
}

struct GemmJob { const float* A; const float* B; float* C; };

__global__ __launch_bounds__(256, 2)
void gemm_small3(GemmJob j0, GemmJob j1, GemmJob j2)
{
    GemmJob j = (blockIdx.z == 0) ? j0 : ((blockIdx.z == 1) ? j1 : j2);
    gemm8_body<false>(j.A, j.B, j.C, 128, 4, blockIdx.x, 0, 64);
}

__global__ __launch_bounds__(256, 2)
void gemm_small1(const float* __restrict__ A, const float* __restrict__ B,
                 float* __restrict__ C)
{
    gemm8_body<false>(A, B, C, 128, 4, blockIdx.x, 0, 64);
}

// ------------------------ reduce / epilogue kernels --------------------------
__global__ void reduce_msg_k(const float* __restrict__ P, const float* __restrict__ ew,
                             float* __restrict__ out)
{
    const int i = blockIdx.x * 256 + threadIdx.x;
    float s = 0.f;
#pragma unroll
    for (int j = 0; j < 8; ++j) s += P[(size_t)j * (4096 * 128) + i];
    out[i] = s * ew[i >> 7];
}

__global__ void reduce_x1_k(const float* __restrict__ P, const float* __restrict__ U,
                            const float* __restrict__ bias, float* __restrict__ X1)
{
    const int i = blockIdx.x * 256 + threadIdx.x;
    float s = U[i] + bias[i & 127];
#pragma unroll
    for (int j = 0; j < 4; ++j) s += P[(size_t)j * (8192 * 128) + i];
    s = (s >= 0.f) ? s : 0.01f * s;
    const unsigned bits = jax_dropout_bits((unsigned)i);
    X1[i] = (bits & 0x80000000u) ? 0.f : (s + s);
}

__global__ void reduce_x2_k(const float* __restrict__ P, const float* __restrict__ U,
                            const float* __restrict__ bias, float* __restrict__ X2)
{
    const int i = blockIdx.x * 256 + threadIdx.x;
    float s = U[i] + bias[i & 127];
#pragma unroll
    for (int j = 0; j < 4; ++j) s += P[(size_t)j * (8192 * 128) + i];
    s = (s >= 0.f) ? s : 0.01f * s;
    s = (s >= 0.f) ? s : 0.01f * s;
    X2[i] = s;
}

__global__ void fc_k(const float* __restrict__ X, const float* __restrict__ state,
                     const float* __restrict__ fcw, const float* __restrict__ fcb,
                     float* __restrict__ out)
{
    const int n = blockIdx.x * 256 + threadIdx.x;
    const float4* xr = (const float4*)(X + (size_t)n * 128);
    const float4* w4 = (const float4*)fcw;
    float s = 0.f;
#pragma unroll
    for (int i = 0; i < 32; ++i) {
        float4 a = xr[i], b = w4[i];
        s += a.x * b.x + a.y * b.y + a.z * b.z + a.w * b.w;
    }
    out[n] = s + state[n] * fcw[128] + fcb[0];
}

// --------------------------------- launch ------------------------------------
extern "C" void kernel_launch(void* const* d_in, const int* in_sizes, int n_in,
                              void* d_out, int out_size)
{
    const float* xi   = (const float*)d_in[0];
    const float* x    = (const float*)d_in[1];
    const float* Ht   = (const float*)d_in[2];
    const float* Hs   = (const float*)d_in[3];
    const float* st   = (const float*)d_in[4];
    const float* w0   = (const float*)d_in[5];
    const float* th0  = (const float*)d_in[6];
    const float* ew0  = (const float*)d_in[7];
    const float* b0   = (const float*)d_in[8];
    const float* w1   = (const float*)d_in[9];
    const float* th1  = (const float*)d_in[10];
    const float* ew1  = (const float*)d_in[11];
    const float* b1   = (const float*)d_in[12];
    const float* fcw  = (const float*)d_in[13];
    const float* fcb  = (const float*)d_in[14];
    float* out = (float*)d_out;

    float *T, *U, *U1, *X, *M, *MP, *ZP;
    cudaGetSymbolAddress((void**)&T,  g_T);
    cudaGetSymbolAddress((void**)&U,  g_U);
    cudaGetSymbolAddress((void**)&U1, g_U1);
    cudaGetSymbolAddress((void**)&X,  g_X);
    cudaGetSymbolAddress((void**)&M,  g_msg);
    cudaGetSymbolAddress((void**)&MP, g_msgP);
    cudaGetSymbolAddress((void**)&ZP, g_ZP);

    cudaFuncSetAttribute(gemm_big<false>, cudaFuncAttributeMaxDynamicSharedMemorySize, SM_BYTES);
    cudaFuncSetAttribute(gemm_big<true>,  cudaFuncAttributeMaxDynamicSharedMemorySize, SM_BYTES);
    cudaFuncSetAttribute(gemm_small3,     cudaFuncAttributeMaxDynamicSharedMemorySize, SM_BYTES);
    cudaFuncSetAttribute(gemm_small1,     cudaFuncAttributeMaxDynamicSharedMemorySize, SM_BYTES);

    // independent small GEMMs: T = x@th0, U = xi@w0, U1 = xi@w1
    GemmJob j0 = { x,  th0, T  };
    GemmJob j1 = { xi, w0,  U  };
    GemmJob j2 = { xi, w1,  U1 };
    gemm_small3<<<dim3(64, 1, 3), 256, SM_BYTES>>>(j0, j1, j2);

    // ---- layer 0 ----
    gemm_big<false><<<dim3(32, 8), 256, SM_BYTES>>>(Hs, T, MP, 8192, 32);
    reduce_msg_k<<<2048, 256>>>(MP, ew0, M);
    gemm_big<true ><<<dim3(64, 4), 256, SM_BYTES>>>(Ht, M, ZP, 8192, 32);
    reduce_x1_k<<<4096, 256>>>(ZP, U, b0, X);

    // ---- layer 1 ----
    gemm_small1<<<64, 256, SM_BYTES>>>(X, th1, T);
    gemm_big<false><<<dim3(32, 8), 256, SM_BYTES>>>(Hs, T, MP, 8192, 32);
    reduce_msg_k<<<2048, 256>>>(MP, ew1, M);
    gemm_big<true ><<<dim3(64, 4), 256, SM_BYTES>>>(Ht, M, ZP, 8192, 32);
    reduce_x2_k<<<4096, 256>>>(ZP, U1, b1, X);

    // ---- head ----
    fc_k<<<32, 256>>>(X, st, fcw, fcb, out);
}